// round 13
// baseline (speedup 1.0000x reference)
#include <cuda_runtime.h>
#include <cuda_bf16.h>
#include <cstdint>

#define Bn 4
#define Tn 2048
#define Cn 1024
#define HDn 64
#define NROWS (Bn*Tn)       // 8192
#define CHUNK 256
#define NCHUNK (Tn/CHUNK)   // 8

typedef unsigned short u16;

// Scratch (__device__ globals — allowed)
__device__ __nv_bfloat16 g_xhi[NROWS*Cn];
__device__ __nv_bfloat16 g_xlo[NROWS*Cn];
__device__ __nv_bfloat16 g_whi[Cn*192];      // [k][Q|K|V cols]
__device__ __nv_bfloat16 g_wlo[Cn*192];
__device__ __nv_bfloat16 g_qhi[NROWS*HDn];
__device__ __nv_bfloat16 g_qlo[NROWS*HDn];
__device__ __nv_bfloat16 g_khi[NROWS*HDn];
__device__ __nv_bfloat16 g_klo[NROWS*HDn];
__device__ __nv_bfloat16 g_vhi[NROWS*HDn];
__device__ __nv_bfloat16 g_vlo[NROWS*HDn];
__device__ float g_s[NROWS*Tn];              // raw scores z (unscaled)
__device__ __nv_bfloat16 g_ehi[NROWS*Tn];    // e = exp(w1), causal, bf16 hi
__device__ __nv_bfloat16 g_elo[NROWS*Tn];    // bf16 lo
__device__ float g_iden[NROWS];              // 1 / causal denominator
__device__ float g_part[NCHUNK*NROWS*HDn];   // split-s partial numerators

// ---- mma.sync helpers ----------------------------------------------------
__device__ __forceinline__ uint32_t smem_u32(const void* p) {
    uint32_t a;
    asm("{ .reg .u64 t; cvta.to.shared.u64 t, %1; cvt.u32.u64 %0, t; }"
        : "=r"(a) : "l"(p));
    return a;
}
#define SW128(o) ((o) ^ (((o) >> 3) & 0x70))

__device__ __forceinline__ void ldsm4(uint32_t* r, uint32_t addr) {
    asm volatile("ldmatrix.sync.aligned.m8n8.x4.shared.b16 {%0,%1,%2,%3}, [%4];"
                 : "=r"(r[0]), "=r"(r[1]), "=r"(r[2]), "=r"(r[3]) : "r"(addr));
}
__device__ __forceinline__ void ldsm4t(uint32_t* r, uint32_t addr) {
    asm volatile("ldmatrix.sync.aligned.m8n8.x4.trans.shared.b16 {%0,%1,%2,%3}, [%4];"
                 : "=r"(r[0]), "=r"(r[1]), "=r"(r[2]), "=r"(r[3]) : "r"(addr));
}
__device__ __forceinline__ void mma16816(float* c, const uint32_t* a,
                                         uint32_t b0, uint32_t b1) {
    asm volatile("mma.sync.aligned.m16n8k16.row.col.f32.bf16.bf16.f32 "
                 "{%0,%1,%2,%3}, {%4,%5,%6,%7}, {%8,%9}, {%0,%1,%2,%3};"
                 : "+f"(c[0]), "+f"(c[1]), "+f"(c[2]), "+f"(c[3])
                 : "r"(a[0]), "r"(a[1]), "r"(a[2]), "r"(a[3]), "r"(b0), "r"(b1));
}
__device__ __forceinline__ uint32_t bfsplit(float v, u16& lo16) {
    __nv_bfloat16 hi = __float2bfloat16(v);
    __nv_bfloat16 lo = __float2bfloat16(v - __bfloat162float(hi));
    lo16 = *(const u16*)&lo;
    return *(const u16*)&hi;
}

// ---------------------------------------------------------------------------
// prep_x: split x (fp32) -> bf16 hi/lo.  8 elems per thread.
// ---------------------------------------------------------------------------
__global__ __launch_bounds__(256) void prep_x(const float* __restrict__ x)
{
    const size_t i8 = ((size_t)blockIdx.x * 256 + threadIdx.x) * 8;
    float4 a = *(const float4*)&x[i8];
    float4 b = *(const float4*)&x[i8 + 4];
    float v[8] = {a.x,a.y,a.z,a.w,b.x,b.y,b.z,b.w};
    u16 hi[8], lo[8];
    #pragma unroll
    for (int j = 0; j < 8; j++) { hi[j] = (u16)bfsplit(v[j], lo[j]); }
    *(uint4*)&g_xhi[i8] = *(const uint4*)hi;
    *(uint4*)&g_xlo[i8] = *(const uint4*)lo;
}

// ---------------------------------------------------------------------------
// prep_w: split Wq|Wk|Wv into combined [k][192] bf16 hi/lo.
// ---------------------------------------------------------------------------
__global__ __launch_bounds__(256) void prep_w(
    const float* __restrict__ Wq, const float* __restrict__ Wk,
    const float* __restrict__ Wv)
{
    const int i8 = (blockIdx.x * 256 + threadIdx.x) * 8;   // over 1024*192
    if (i8 >= Cn*192) return;
    const int k    = i8 / 192;
    const int col8 = i8 - k*192;
    const float* W = (col8 < 64) ? Wq : ((col8 < 128) ? Wk : Wv);
    const float* src = &W[(size_t)k*HDn + (col8 & 63)];
    float4 a = *(const float4*)&src[0];
    float4 b = *(const float4*)&src[4];
    float v[8] = {a.x,a.y,a.z,a.w,b.x,b.y,b.z,b.w};
    u16 hi[8], lo[8];
    #pragma unroll
    for (int j = 0; j < 8; j++) { hi[j] = (u16)bfsplit(v[j], lo[j]); }
    *(uint4*)&g_whi[i8] = *(const uint4*)hi;
    *(uint4*)&g_wlo[i8] = *(const uint4*)lo;
}

// ---------------------------------------------------------------------------
// qkv_mma: [8192,1024] @ [1024,192] via HMMA, 3-term bf16 split.
// grid (2 col-halves of 96, 64 row-blocks of 128); 256 thr; 8 warps 4m x 2n;
// warp tile 32 rows x 48 cols.  x/W loaded PRE-SPLIT (pure uint4 staging).
// ---------------------------------------------------------------------------
#define XSTR 40    // halves per x row (32 -> 40)
#define WSTR 104   // halves per w row (96 -> 104)

__global__ __launch_bounds__(256) void qkv_mma()
{
    __shared__ u16 sxh[128*XSTR], sxl[128*XSTR];
    __shared__ u16 swh[32*WSTR],  swl[32*WSTR];

    const int ch   = blockIdx.x;
    const int row0 = blockIdx.y * 128;
    const int col0 = ch * 96;
    const int tid  = threadIdx.x;
    const int wid  = tid >> 5;
    const int lane = tid & 31;
    const int wm   = wid & 3;        // rows wm*32..+31
    const int wn   = wid >> 2;       // cols wn*48..+47

    const uint32_t sb_xh = smem_u32(sxh), sb_xl = smem_u32(sxl);
    const uint32_t sb_wh = smem_u32(swh), sb_wl = smem_u32(swl);

    float c[2][6][4];
    #pragma unroll
    for (int mt = 0; mt < 2; mt++)
        #pragma unroll
        for (int nt = 0; nt < 6; nt++)
            #pragma unroll
            for (int q = 0; q < 4; q++) c[mt][nt][q] = 0.f;

    const int lrow  = lane & 15;
    const int lcolb = (lane >> 4) * 16;

    for (int k0 = 0; k0 < Cn; k0 += 32) {
        __syncthreads();
        // x tile: 128 rows x 32 k halves (pre-split, pure copies)
        #pragma unroll
        for (int i = tid; i < 512; i += 256) {
            int r = i >> 2, c8 = (i & 3) * 8;
            size_t go = (size_t)(row0 + r)*Cn + k0 + c8;
            *(uint4*)&sxh[r*XSTR + c8] = *(const uint4*)&g_xhi[go];
            *(uint4*)&sxl[r*XSTR + c8] = *(const uint4*)&g_xlo[go];
        }
        // W tile: 32 k x 96 cols (pre-split)
        for (int i = tid; i < 384; i += 256) {
            int r = i / 12, c8 = (i % 12) * 8;
            size_t go = (size_t)(k0 + r)*192 + col0 + c8;
            *(uint4*)&swh[r*WSTR + c8] = *(const uint4*)&g_whi[go];
            *(uint4*)&swl[r*WSTR + c8] = *(const uint4*)&g_wlo[go];
        }
        __syncthreads();
        #pragma unroll
        for (int ks = 0; ks < 2; ks++) {
            uint32_t ah[2][4], al[2][4];
            #pragma unroll
            for (int mt = 0; mt < 2; mt++) {
                uint32_t base = (wm*32 + mt*16 + lrow)*(XSTR*2) + ks*32 + lcolb;
                ldsm4(ah[mt], sb_xh + base);
                ldsm4(al[mt], sb_xl + base);
            }
            uint32_t bh[3][4], bl[3][4];
            #pragma unroll
            for (int ng = 0; ng < 3; ng++) {
                uint32_t base = (ks*16 + lrow)*(WSTR*2) + (wn*48 + ng*16)*2 + lcolb;
                ldsm4t(bh[ng], sb_wh + base);
                ldsm4t(bl[ng], sb_wl + base);
            }
            #pragma unroll
            for (int mt = 0; mt < 2; mt++) {
                #pragma unroll
                for (int ng = 0; ng < 3; ng++) {
                    float* c0 = c[mt][ng*2+0];
                    float* c1 = c[mt][ng*2+1];
                    mma16816(c0, ah[mt], bh[ng][0], bh[ng][1]);
                    mma16816(c1, ah[mt], bh[ng][2], bh[ng][3]);
                    mma16816(c0, ah[mt], bl[ng][0], bl[ng][1]);
                    mma16816(c1, ah[mt], bl[ng][2], bl[ng][3]);
                    mma16816(c0, al[mt], bh[ng][0], bh[ng][1]);
                    mma16816(c1, al[mt], bh[ng][2], bh[ng][3]);
                }
            }
        }
    }

    // epilogue: split to bf16 hi/lo, scatter to q/k/v
    #pragma unroll
    for (int mt = 0; mt < 2; mt++) {
        #pragma unroll
        for (int nt = 0; nt < 6; nt++) {
            #pragma unroll
            for (int h = 0; h < 2; h++) {
                int r  = row0 + wm*32 + mt*16 + (lane >> 2) + h*8;
                int gc = col0 + wn*48 + nt*8 + (lane & 3)*2;
                float v0 = c[mt][nt][h*2+0], v1 = c[mt][nt][h*2+1];
                u16 lo0, lo1;
                u16 hi0 = (u16)bfsplit(v0, lo0);
                u16 hi1 = (u16)bfsplit(v1, lo1);
                uint32_t hip = (uint32_t)hi0 | ((uint32_t)hi1 << 16);
                uint32_t lop = (uint32_t)lo0 | ((uint32_t)lo1 << 16);
                int dcol = gc & 63;
                size_t o = (size_t)r*HDn + dcol;
                if      (gc < 64)  { *(uint32_t*)&g_qhi[o] = hip; *(uint32_t*)&g_qlo[o] = lop; }
                else if (gc < 128) { *(uint32_t*)&g_khi[o] = hip; *(uint32_t*)&g_klo[o] = lop; }
                else               { *(uint32_t*)&g_vhi[o] = hip; *(uint32_t*)&g_vlo[o] = lop; }
            }
        }
    }
}

// ---------------------------------------------------------------------------
// Kernel B1: scores via warp-level mma.sync (bf16 split, fp32 accum).
// ---------------------------------------------------------------------------
#define SC_QHI     0
#define SC_QLO     (SC_QHI + 16384)
#define SC_KHI     (SC_QLO + 16384)
#define SC_KLO     (SC_KHI + 16384)
#define SC_SMEM    (SC_KLO + 16384)

__device__ __forceinline__ void sc_load_tile(char* smem, int dstoff,
    const __nv_bfloat16* __restrict__ src, int row0, int tid)
{
    #pragma unroll
    for (int c = tid; c < 1024; c += 256) {
        int r = c >> 3, o = (c & 7) * 16;
        uint4 v = *(const uint4*)((const char*)(src + (size_t)(row0 + r)*HDn) + o);
        *(uint4*)(smem + dstoff + SW128(r*128 + o)) = v;
    }
}

__global__ __launch_bounds__(256) void scores_mma()
{
    extern __shared__ char smem[];
    const uint32_t sb = smem_u32(smem);
    const int tid  = threadIdx.x;
    const int wid  = tid >> 5;
    const int lane = tid & 31;

    const int s0    = blockIdx.x * 128;
    const int row0  = blockIdx.y * 128;
    const int b     = row0 >> 11;
    const int krow0 = b * Tn + s0;

    sc_load_tile(smem, SC_QHI, g_qhi, row0, tid);
    sc_load_tile(smem, SC_QLO, g_qlo, row0, tid);
    sc_load_tile(smem, SC_KHI, g_khi, krow0, tid);
    sc_load_tile(smem, SC_KLO, g_klo, krow0, tid);
    __syncthreads();

    const int wm = wid & 3;
    const int wn = wid >> 2;

    float c[2][8][4];
    #pragma unroll
    for (int mt = 0; mt < 2; mt++)
        #pragma unroll
        for (int nt = 0; nt < 8; nt++)
            #pragma unroll
            for (int q = 0; q < 4; q++) c[mt][nt][q] = 0.f;

    const int lrow = lane & 15;
    const int lcol = (lane >> 4) * 16;

    #pragma unroll
    for (int k = 0; k < 4; k++) {
        const int kb = k * 32;
        uint32_t ahi[2][4], alo[2][4];
        #pragma unroll
        for (int mt = 0; mt < 2; mt++) {
            int r = wm*32 + mt*16 + lrow;
            ldsm4(ahi[mt], sb + SC_QHI + SW128(r*128 + kb + lcol));
            ldsm4(alo[mt], sb + SC_QLO + SW128(r*128 + kb + lcol));
        }
        #pragma unroll
        for (int nt2 = 0; nt2 < 4; nt2++) {
            int r = wn*64 + nt2*16 + lrow;
            uint32_t bh[4], bl[4];
            ldsm4(bh, sb + SC_KHI + SW128(r*128 + kb + lcol));
            ldsm4(bl, sb + SC_KLO + SW128(r*128 + kb + lcol));
            #pragma unroll
            for (int mt = 0; mt < 2; mt++) {
                float* c0 = c[mt][nt2*2+0];
                float* c1 = c[mt][nt2*2+1];
                mma16816(c0, ahi[mt], bh[0], bh[2]);
                mma16816(c1, ahi[mt], bh[1], bh[3]);
                mma16816(c0, ahi[mt], bl[0], bl[2]);
                mma16816(c1, ahi[mt], bl[1], bl[3]);
                mma16816(c0, alo[mt], bh[0], bh[2]);
                mma16816(c1, alo[mt], bh[1], bh[3]);
            }
        }
    }

    #pragma unroll
    for (int mt = 0; mt < 2; mt++) {
        #pragma unroll
        for (int nt = 0; nt < 8; nt++) {
            int row = row0 + wm*32 + mt*16 + (lane >> 2);
            int col = s0 + wn*64 + nt*8 + (lane & 3)*2;
            *(float2*)&g_s[(size_t)row*Tn + col]     = make_float2(c[mt][nt][0], c[mt][nt][1]);
            *(float2*)&g_s[(size_t)(row+8)*Tn + col] = make_float2(c[mt][nt][2], c[mt][nt][3]);
        }
    }
}

// ---------------------------------------------------------------------------
// Kernel B2: per-row stats + e materialization (causal-skipped).
// ---------------------------------------------------------------------------
__global__ __launch_bounds__(256) void stats_kernel()
{
    const int row  = blockIdx.x * 8 + (threadIdx.x >> 5);
    const int lane = threadIdx.x & 31;
    const int t    = row & (Tn - 1);
    const float* zr = &g_s[(size_t)row * Tn];

    float4 v[16];
    #pragma unroll
    for (int w = 0; w < 16; w++)
        v[w] = *(const float4*)&zr[w*128 + lane*4];

    float m = -1e30f;
    #pragma unroll
    for (int w = 0; w < 16; w++)
        m = fmaxf(m, fmaxf(fmaxf(v[w].x, v[w].y), fmaxf(v[w].z, v[w].w)));
    #pragma unroll
    for (int off = 16; off > 0; off >>= 1)
        m = fmaxf(m, __shfl_xor_sync(0xffffffffu, m, off));
    const float m8 = 8.f * m;

    float Z = 0.f;
    #pragma unroll
    for (int w = 0; w < 16; w++) {
        v[w].x = __expf(fmaf(v[w].x, 8.f, -m8));
        v[w].y = __expf(fmaf(v[w].y, 8.f, -m8));
        v[w].z = __expf(fmaf(v[w].z, 8.f, -m8));
        v[w].w = __expf(fmaf(v[w].w, 8.f, -m8));
        Z += v[w].x + v[w].y + v[w].z + v[w].w;
    }
    #pragma unroll
    for (int off = 16; off > 0; off >>= 1)
        Z += __shfl_xor_sync(0xffffffffu, Z, off);
    const float iz = 1.f / Z;

    const int wmax = t >> 7;    // last consumed 128-key group (warp-uniform)
    float den = 0.f;
    #pragma unroll
    for (int w = 0; w < 16; w++) {
        if (w <= wmax) {
            const int sbase = w*128 + lane*4;
            float e0 = (sbase + 0 <= t) ? __expf(v[w].x * iz) : 0.f;
            float e1 = (sbase + 1 <= t) ? __expf(v[w].y * iz) : 0.f;
            float e2 = (sbase + 2 <= t) ? __expf(v[w].z * iz) : 0.f;
            float e3 = (sbase + 3 <= t) ? __expf(v[w].w * iz) : 0.f;
            den += e0 + e1 + e2 + e3;
            u16 hi[4], lo[4];
            hi[0] = (u16)bfsplit(e0, lo[0]);
            hi[1] = (u16)bfsplit(e1, lo[1]);
            hi[2] = (u16)bfsplit(e2, lo[2]);
            hi[3] = (u16)bfsplit(e3, lo[3]);
            *(uint2*)&g_ehi[(size_t)row*Tn + sbase] = *(const uint2*)hi;
            *(uint2*)&g_elo[(size_t)row*Tn + sbase] = *(const uint2*)lo;
        }
    }
    #pragma unroll
    for (int off = 16; off > 0; off >>= 1)
        den += __shfl_xor_sync(0xffffffffu, den, off);

    if (lane == 0) g_iden[row] = 1.f / den;
}

// ---------------------------------------------------------------------------
// Kernel B3: split-s partial numerators — pure staged HMMA GEMM.
// ---------------------------------------------------------------------------
#define ESTR 40   // halves per e row (32 -> 40)
#define VSTR 72   // halves per v row (64 -> 72)

__global__ __launch_bounds__(256) void outp_mma()
{
    __shared__ u16 seh[128*ESTR], sel[128*ESTR];
    __shared__ u16 svh[32*VSTR],  svl[32*VSTR];

    const int chunk = blockIdx.x;
    const int row0  = blockIdx.y * 128;
    const int b     = row0 >> 11;
    const int t0    = row0 & (Tn - 1);
    const int sbeg  = chunk * CHUNK;
    if (sbeg > t0 + 127) return;
    const int send  = min(sbeg + CHUNK, t0 + 128);
    const int nk    = (send - sbeg) >> 5;

    const int tid  = threadIdx.x;
    const int wid  = tid >> 5;
    const int lane = tid & 31;
    const int wm   = wid & 3;
    const int wn   = wid >> 2;

    const uint32_t sb_eh = smem_u32(seh), sb_el = smem_u32(sel);
    const uint32_t sb_vh = smem_u32(svh), sb_vl = smem_u32(svl);

    float c[2][4][4];
    #pragma unroll
    for (int mt = 0; mt < 2; mt++)
        #pragma unroll
        for (int nt = 0; nt < 4; nt++)
            #pragma unroll
            for (int q = 0; q < 4; q++) c[mt][nt][q] = 0.f;

    const int lrow  = lane & 15;
    const int lcolb = (lane >> 4) * 16;

    for (int kt = 0; kt < nk; kt++) {
        const int s0 = sbeg + kt*32;
        __syncthreads();
        // e tiles: 128 rows x 32 s
        #pragma unroll
        for (int i = tid; i < 512; i += 256) {
            int r = i >> 2, c8 = (i & 3) * 8;
            size_t go = (size_t)(row0 + r)*Tn + s0 + c8;
            *(uint4*)&seh[r*ESTR + c8] = *(const uint4*)&g_ehi[go];
            *(uint4*)&sel[r*ESTR + c8] = *(const uint4*)&g_elo[go];
        }
        // V tiles: 32 s x 64 d
        {
            int r = tid >> 3, c8 = (tid & 7) * 8;
            size_t go = (size_t)(b*Tn + s0 + r)*HDn + c8;
            *(uint4*)&svh[r*VSTR + c8] = *(const uint4*)&g_vhi[go];
            *(uint4*)&svl[r*VSTR + c8] = *(const uint4*)&g_vlo[go];
        }
        __syncthreads();
        #pragma unroll
        for (int ks = 0; ks < 2; ks++) {
            uint32_t ah[2][4], al[2][4];
            #pragma unroll
            for (int mt = 0; mt < 2; mt++) {
                uint32_t base = (wm*32 + mt*16 + lrow)*(ESTR*2) + ks*32 + lcolb;
                ldsm4(ah[mt], sb_eh + base);
                ldsm4(al[mt], sb_el + base);
            }
            uint32_t bh[2][4], bl[2][4];
            #pragma unroll
            for (int ng = 0; ng < 2; ng++) {
                uint32_t base = (ks*16 + lrow)*(VSTR*2) + (wn*32 + ng*16)*2 + lcolb;
                ldsm4t(bh[ng], sb_vh + base);
                ldsm4t(bl[ng], sb_vl + base);
            }
            #pragma unroll
            for (int mt = 0; mt < 2; mt++) {
                #pragma unroll
                for (int ng = 0; ng < 2; ng++) {
                    float* c0 = c[mt][ng*2+0];
                    float* c1 = c[mt][ng*2+1];
                    mma16816(c0, ah[mt], bh[ng][0], bh[ng][1]);
                    mma16816(c1, ah[mt], bh[ng][2], bh[ng][3]);
                    mma16816(c0, ah[mt], bl[ng][0], bl[ng][1]);
                    mma16816(c1, ah[mt], bl[ng][2], bl[ng][3]);
                    mma16816(c0, al[mt], bh[ng][0], bh[ng][1]);
                    mma16816(c1, al[mt], bh[ng][2], bh[ng][3]);
                }
            }
        }
    }

    float* dst = &g_part[((size_t)chunk*NROWS + row0)*HDn];
    #pragma unroll
    for (int mt = 0; mt < 2; mt++) {
        #pragma unroll
        for (int nt = 0; nt < 4; nt++) {
            int r   = wm*32 + mt*16 + (lane >> 2);
            int col = wn*32 + nt*8 + (lane & 3)*2;
            *(float2*)&dst[(size_t)r*HDn + col]     = make_float2(c[mt][nt][0], c[mt][nt][1]);
            *(float2*)&dst[(size_t)(r+8)*HDn + col] = make_float2(c[mt][nt][2], c[mt][nt][3]);
        }
    }
}

// ---------------------------------------------------------------------------
// Kernel B4: finalize.
// ---------------------------------------------------------------------------
__global__ __launch_bounds__(256) void fin_kernel(float* __restrict__ out)
{
    const int idx = blockIdx.x * 256 + threadIdx.x;
    const int row = idx >> 4;
    const int d4  = (idx & 15) * 4;
    const int nch = (((row & (Tn-1)) | 127) / CHUNK) + 1;

    float4 s = make_float4(0.f, 0.f, 0.f, 0.f);
    for (int c = 0; c < nch; c++) {
        float4 p = *(const float4*)&g_part[((size_t)c*NROWS + row)*HDn + d4];
        s.x += p.x; s.y += p.y; s.z += p.z; s.w += p.w;
    }
    const float inv = g_iden[row];
    s.x *= inv; s.y *= inv; s.z *= inv; s.w *= inv;
    *(float4*)&out[(size_t)row*HDn + d4] = s;
}

// ---------------------------------------------------------------------------
extern "C" void kernel_launch(void* const* d_in, const int* in_sizes, int n_in,
                              void* d_out, int out_size)
{
    const float* x  = (const float*)d_in[0];
    const float* Wq = (const float*)d_in[1];
    const float* Wk = (const float*)d_in[2];
    const float* Wv = (const float*)d_in[3];
    float* out = (float*)d_out;

    cudaFuncSetAttribute(scores_mma, cudaFuncAttributeMaxDynamicSharedMemorySize, SC_SMEM);

    prep_x<<<(NROWS*Cn/8)/256, 256>>>(x);
    prep_w<<<(Cn*192/8 + 255)/256, 256>>>(Wq, Wk, Wv);
    qkv_mma<<<dim3(2, NROWS/128), 256>>>();
    scores_mma<<<dim3(Tn/128, NROWS/128), 256, SC_SMEM>>>();
    stats_kernel<<<NROWS/8, 256>>>();
    outp_mma<<<dim3(NCHUNK, NROWS/128), 256>>>();
    fin_kernel<<<(NROWS*HDn/4)/256, 256>>>(out);
}

// round 14
// speedup vs baseline: 1.0648x; 1.0648x over previous
#include <cuda_runtime.h>
#include <cuda_bf16.h>
#include <cstdint>

#define Bn 4
#define Tn 2048
#define Cn 1024
#define HDn 64
#define NROWS (Bn*Tn)       // 8192
#define CHUNK 256
#define NCHUNK (Tn/CHUNK)   // 8

typedef unsigned short u16;

// Scratch (__device__ globals — allowed)
__device__ __nv_bfloat16 g_xhi[NROWS*Cn];
__device__ __nv_bfloat16 g_xlo[NROWS*Cn];
__device__ __nv_bfloat16 g_whi[Cn*192];      // [k][Q|K|V cols]
__device__ __nv_bfloat16 g_wlo[Cn*192];
__device__ __nv_bfloat16 g_qhi[NROWS*HDn];
__device__ __nv_bfloat16 g_qlo[NROWS*HDn];
__device__ __nv_bfloat16 g_khi[NROWS*HDn];
__device__ __nv_bfloat16 g_klo[NROWS*HDn];
__device__ __nv_bfloat16 g_vhi[NROWS*HDn];
__device__ __nv_bfloat16 g_vlo[NROWS*HDn];
__device__ float g_s[NROWS*Tn];              // raw scores z (unscaled)
__device__ __nv_bfloat16 g_ehi[NROWS*Tn];    // e = exp(w1), causal, bf16 hi
__device__ __nv_bfloat16 g_elo[NROWS*Tn];    // bf16 lo
__device__ float g_iden[NROWS];              // 1 / causal denominator
__device__ float g_part[NCHUNK*NROWS*HDn];   // split-s partial numerators

// ---- mma.sync helpers ----------------------------------------------------
__device__ __forceinline__ uint32_t smem_u32(const void* p) {
    uint32_t a;
    asm("{ .reg .u64 t; cvta.to.shared.u64 t, %1; cvt.u32.u64 %0, t; }"
        : "=r"(a) : "l"(p));
    return a;
}
#define SW128(o) ((o) ^ (((o) >> 3) & 0x70))

__device__ __forceinline__ void ldsm4(uint32_t* r, uint32_t addr) {
    asm volatile("ldmatrix.sync.aligned.m8n8.x4.shared.b16 {%0,%1,%2,%3}, [%4];"
                 : "=r"(r[0]), "=r"(r[1]), "=r"(r[2]), "=r"(r[3]) : "r"(addr));
}
__device__ __forceinline__ void ldsm4t(uint32_t* r, uint32_t addr) {
    asm volatile("ldmatrix.sync.aligned.m8n8.x4.trans.shared.b16 {%0,%1,%2,%3}, [%4];"
                 : "=r"(r[0]), "=r"(r[1]), "=r"(r[2]), "=r"(r[3]) : "r"(addr));
}
__device__ __forceinline__ void mma16816(float* c, const uint32_t* a,
                                         uint32_t b0, uint32_t b1) {
    asm volatile("mma.sync.aligned.m16n8k16.row.col.f32.bf16.bf16.f32 "
                 "{%0,%1,%2,%3}, {%4,%5,%6,%7}, {%8,%9}, {%0,%1,%2,%3};"
                 : "+f"(c[0]), "+f"(c[1]), "+f"(c[2]), "+f"(c[3])
                 : "r"(a[0]), "r"(a[1]), "r"(a[2]), "r"(a[3]), "r"(b0), "r"(b1));
}
__device__ __forceinline__ uint32_t bfsplit(float v, u16& lo16) {
    __nv_bfloat16 hi = __float2bfloat16(v);
    __nv_bfloat16 lo = __float2bfloat16(v - __bfloat162float(hi));
    lo16 = *(const u16*)&lo;
    return *(const u16*)&hi;
}

// ---------------------------------------------------------------------------
// prep_x: split x (fp32) -> bf16 hi/lo.  8 elems per thread.
// ---------------------------------------------------------------------------
__global__ __launch_bounds__(256) void prep_x(const float* __restrict__ x)
{
    const size_t i8 = ((size_t)blockIdx.x * 256 + threadIdx.x) * 8;
    float4 a = *(const float4*)&x[i8];
    float4 b = *(const float4*)&x[i8 + 4];
    float v[8] = {a.x,a.y,a.z,a.w,b.x,b.y,b.z,b.w};
    u16 hi[8], lo[8];
    #pragma unroll
    for (int j = 0; j < 8; j++) { hi[j] = (u16)bfsplit(v[j], lo[j]); }
    *(uint4*)&g_xhi[i8] = *(const uint4*)hi;
    *(uint4*)&g_xlo[i8] = *(const uint4*)lo;
}

// ---------------------------------------------------------------------------
// prep_w: split Wq|Wk|Wv into combined [k][192] bf16 hi/lo.
// ---------------------------------------------------------------------------
__global__ __launch_bounds__(256) void prep_w(
    const float* __restrict__ Wq, const float* __restrict__ Wk,
    const float* __restrict__ Wv)
{
    const int i8 = (blockIdx.x * 256 + threadIdx.x) * 8;   // over 1024*192
    if (i8 >= Cn*192) return;
    const int k    = i8 / 192;
    const int col8 = i8 - k*192;
    const float* W = (col8 < 64) ? Wq : ((col8 < 128) ? Wk : Wv);
    const float* src = &W[(size_t)k*HDn + (col8 & 63)];
    float4 a = *(const float4*)&src[0];
    float4 b = *(const float4*)&src[4];
    float v[8] = {a.x,a.y,a.z,a.w,b.x,b.y,b.z,b.w};
    u16 hi[8], lo[8];
    #pragma unroll
    for (int j = 0; j < 8; j++) { hi[j] = (u16)bfsplit(v[j], lo[j]); }
    *(uint4*)&g_whi[i8] = *(const uint4*)hi;
    *(uint4*)&g_wlo[i8] = *(const uint4*)lo;
}

// ---------------------------------------------------------------------------
// qkv_mma (r12 tiling + double buffer): [8192,1024]@[1024,192] HMMA 3-term.
// grid (2 col-halves of 96, 128 row-blocks of 64); 256 thr; 8 warps 4m x 2n;
// warp tile 16 rows x 48 cols.  K staged 32/iter, 2-stage smem pipeline:
// iter i: LDG tile i+1 -> regs; MMA on buf[i&1]; STS regs -> buf[(i+1)&1]; sync.
// ---------------------------------------------------------------------------
#define XSTR 40    // halves per x row (32 -> 40)
#define WSTR 104   // halves per w row (96 -> 104)

__global__ __launch_bounds__(256) void qkv_mma()
{
    __shared__ u16 sxh[2][64*XSTR], sxl[2][64*XSTR];
    __shared__ u16 swh[2][32*WSTR], swl[2][32*WSTR];

    const int ch   = blockIdx.x;
    const int row0 = blockIdx.y * 64;
    const int col0 = ch * 96;
    const int tid  = threadIdx.x;
    const int wid  = tid >> 5;
    const int lane = tid & 31;
    const int wm   = wid & 3;        // rows wm*16..+15
    const int wn   = wid >> 2;       // cols wn*48..+47

    float c[6][4];
    #pragma unroll
    for (int nt = 0; nt < 6; nt++)
        #pragma unroll
        for (int q = 0; q < 4; q++) c[nt][q] = 0.f;

    const int lrow  = lane & 15;
    const int lcolb = (lane >> 4) * 16;

    // staging indices (fixed per thread)
    const int xr = tid >> 2, xc8 = (tid & 3) * 8;          // 1 x-slot/thread
    const int wr0 = tid / 12,          wc0 = (tid % 12) * 8;      // w slot A
    const int wr1 = (tid + 256) / 12,  wc1 = ((tid + 256) % 12) * 8; // w slot B
    const bool hasw1 = (tid + 256) < 384;

    uint4 px_h, px_l, pw_h0, pw_l0, pw_h1, pw_l1;

    // prefetch k0 = 0
    {
        size_t go = (size_t)(row0 + xr)*Cn + xc8;
        px_h = *(const uint4*)&g_xhi[go];
        px_l = *(const uint4*)&g_xlo[go];
        size_t gw0 = (size_t)wr0*192 + col0 + wc0;
        pw_h0 = *(const uint4*)&g_whi[gw0];
        pw_l0 = *(const uint4*)&g_wlo[gw0];
        if (hasw1) {
            size_t gw1 = (size_t)wr1*192 + col0 + wc1;
            pw_h1 = *(const uint4*)&g_whi[gw1];
            pw_l1 = *(const uint4*)&g_wlo[gw1];
        }
    }
    // store to buf 0
    {
        *(uint4*)&sxh[0][xr*XSTR + xc8] = px_h;
        *(uint4*)&sxl[0][xr*XSTR + xc8] = px_l;
        *(uint4*)&swh[0][wr0*WSTR + wc0] = pw_h0;
        *(uint4*)&swl[0][wr0*WSTR + wc0] = pw_l0;
        if (hasw1) {
            *(uint4*)&swh[0][wr1*WSTR + wc1] = pw_h1;
            *(uint4*)&swl[0][wr1*WSTR + wc1] = pw_l1;
        }
    }
    __syncthreads();

    for (int it = 0; it < 32; it++) {
        const int cur = it & 1, nxt = cur ^ 1;
        // prefetch next tile (LDG issues before MMA, latency overlapped)
        if (it < 31) {
            const int k0 = (it + 1) * 32;
            size_t go = (size_t)(row0 + xr)*Cn + k0 + xc8;
            px_h = *(const uint4*)&g_xhi[go];
            px_l = *(const uint4*)&g_xlo[go];
            size_t gw0 = (size_t)(k0 + wr0)*192 + col0 + wc0;
            pw_h0 = *(const uint4*)&g_whi[gw0];
            pw_l0 = *(const uint4*)&g_wlo[gw0];
            if (hasw1) {
                size_t gw1 = (size_t)(k0 + wr1)*192 + col0 + wc1;
                pw_h1 = *(const uint4*)&g_whi[gw1];
                pw_l1 = *(const uint4*)&g_wlo[gw1];
            }
        }
        // MMA on current buffer
        const uint32_t sb_xh = smem_u32(sxh[cur]), sb_xl = smem_u32(sxl[cur]);
        const uint32_t sb_wh = smem_u32(swh[cur]), sb_wl = smem_u32(swl[cur]);
        #pragma unroll
        for (int ks = 0; ks < 2; ks++) {
            uint32_t ah[4], al[4];
            {
                uint32_t base = (wm*16 + lrow)*(XSTR*2) + ks*32 + lcolb;
                ldsm4(ah, sb_xh + base);
                ldsm4(al, sb_xl + base);
            }
            uint32_t bh[3][4], bl[3][4];
            #pragma unroll
            for (int ng = 0; ng < 3; ng++) {
                uint32_t base = (ks*16 + lrow)*(WSTR*2) + (wn*48 + ng*16)*2 + lcolb;
                ldsm4t(bh[ng], sb_wh + base);
                ldsm4t(bl[ng], sb_wl + base);
            }
            #pragma unroll
            for (int ng = 0; ng < 3; ng++) {
                float* c0 = c[ng*2+0];
                float* c1 = c[ng*2+1];
                mma16816(c0, ah, bh[ng][0], bh[ng][1]);
                mma16816(c1, ah, bh[ng][2], bh[ng][3]);
                mma16816(c0, ah, bl[ng][0], bl[ng][1]);
                mma16816(c1, ah, bl[ng][2], bl[ng][3]);
                mma16816(c0, al, bh[ng][0], bh[ng][1]);
                mma16816(c1, al, bh[ng][2], bh[ng][3]);
            }
        }
        // store prefetched tile into next buffer; one sync per iter
        if (it < 31) {
            *(uint4*)&sxh[nxt][xr*XSTR + xc8] = px_h;
            *(uint4*)&sxl[nxt][xr*XSTR + xc8] = px_l;
            *(uint4*)&swh[nxt][wr0*WSTR + wc0] = pw_h0;
            *(uint4*)&swl[nxt][wr0*WSTR + wc0] = pw_l0;
            if (hasw1) {
                *(uint4*)&swh[nxt][wr1*WSTR + wc1] = pw_h1;
                *(uint4*)&swl[nxt][wr1*WSTR + wc1] = pw_l1;
            }
            __syncthreads();
        }
    }

    // epilogue: split to bf16 hi/lo, scatter to q/k/v
    #pragma unroll
    for (int nt = 0; nt < 6; nt++) {
        #pragma unroll
        for (int h = 0; h < 2; h++) {
            int r   = row0 + wm*16 + (lane >> 2) + h*8;
            int gc  = col0 + wn*48 + nt*8 + (lane & 3)*2;
            float v0 = c[nt][h*2+0], v1 = c[nt][h*2+1];
            u16 lo0, lo1;
            u16 hi0 = (u16)bfsplit(v0, lo0);
            u16 hi1 = (u16)bfsplit(v1, lo1);
            uint32_t hip = (uint32_t)hi0 | ((uint32_t)hi1 << 16);
            uint32_t lop = (uint32_t)lo0 | ((uint32_t)lo1 << 16);
            int dcol = gc & 63;
            size_t o = (size_t)r*HDn + dcol;
            if      (gc < 64)  { *(uint32_t*)&g_qhi[o] = hip; *(uint32_t*)&g_qlo[o] = lop; }
            else if (gc < 128) { *(uint32_t*)&g_khi[o] = hip; *(uint32_t*)&g_klo[o] = lop; }
            else               { *(uint32_t*)&g_vhi[o] = hip; *(uint32_t*)&g_vlo[o] = lop; }
        }
    }
}

// ---------------------------------------------------------------------------
// Kernel B1: scores via warp-level mma.sync (bf16 split, fp32 accum).
// ---------------------------------------------------------------------------
#define SC_QHI     0
#define SC_QLO     (SC_QHI + 16384)
#define SC_KHI     (SC_QLO + 16384)
#define SC_KLO     (SC_KHI + 16384)
#define SC_SMEM    (SC_KLO + 16384)

__device__ __forceinline__ void sc_load_tile(char* smem, int dstoff,
    const __nv_bfloat16* __restrict__ src, int row0, int tid)
{
    #pragma unroll
    for (int c = tid; c < 1024; c += 256) {
        int r = c >> 3, o = (c & 7) * 16;
        uint4 v = *(const uint4*)((const char*)(src + (size_t)(row0 + r)*HDn) + o);
        *(uint4*)(smem + dstoff + SW128(r*128 + o)) = v;
    }
}

__global__ __launch_bounds__(256) void scores_mma()
{
    extern __shared__ char smem[];
    const uint32_t sb = smem_u32(smem);
    const int tid  = threadIdx.x;
    const int wid  = tid >> 5;
    const int lane = tid & 31;

    const int s0    = blockIdx.x * 128;
    const int row0  = blockIdx.y * 128;
    const int b     = row0 >> 11;
    const int krow0 = b * Tn + s0;

    sc_load_tile(smem, SC_QHI, g_qhi, row0, tid);
    sc_load_tile(smem, SC_QLO, g_qlo, row0, tid);
    sc_load_tile(smem, SC_KHI, g_khi, krow0, tid);
    sc_load_tile(smem, SC_KLO, g_klo, krow0, tid);
    __syncthreads();

    const int wm = wid & 3;
    const int wn = wid >> 2;

    float c[2][8][4];
    #pragma unroll
    for (int mt = 0; mt < 2; mt++)
        #pragma unroll
        for (int nt = 0; nt < 8; nt++)
            #pragma unroll
            for (int q = 0; q < 4; q++) c[mt][nt][q] = 0.f;

    const int lrow = lane & 15;
    const int lcol = (lane >> 4) * 16;

    #pragma unroll
    for (int k = 0; k < 4; k++) {
        const int kb = k * 32;
        uint32_t ahi[2][4], alo[2][4];
        #pragma unroll
        for (int mt = 0; mt < 2; mt++) {
            int r = wm*32 + mt*16 + lrow;
            ldsm4(ahi[mt], sb + SC_QHI + SW128(r*128 + kb + lcol));
            ldsm4(alo[mt], sb + SC_QLO + SW128(r*128 + kb + lcol));
        }
        #pragma unroll
        for (int nt2 = 0; nt2 < 4; nt2++) {
            int r = wn*64 + nt2*16 + lrow;
            uint32_t bh[4], bl[4];
            ldsm4(bh, sb + SC_KHI + SW128(r*128 + kb + lcol));
            ldsm4(bl, sb + SC_KLO + SW128(r*128 + kb + lcol));
            #pragma unroll
            for (int mt = 0; mt < 2; mt++) {
                float* c0 = c[mt][nt2*2+0];
                float* c1 = c[mt][nt2*2+1];
                mma16816(c0, ahi[mt], bh[0], bh[2]);
                mma16816(c1, ahi[mt], bh[1], bh[3]);
                mma16816(c0, ahi[mt], bl[0], bl[2]);
                mma16816(c1, ahi[mt], bl[1], bl[3]);
                mma16816(c0, alo[mt], bh[0], bh[2]);
                mma16816(c1, alo[mt], bh[1], bh[3]);
            }
        }
    }

    #pragma unroll
    for (int mt = 0; mt < 2; mt++) {
        #pragma unroll
        for (int nt = 0; nt < 8; nt++) {
            int row = row0 + wm*32 + mt*16 + (lane >> 2);
            int col = s0 + wn*64 + nt*8 + (lane & 3)*2;
            *(float2*)&g_s[(size_t)row*Tn + col]     = make_float2(c[mt][nt][0], c[mt][nt][1]);
            *(float2*)&g_s[(size_t)(row+8)*Tn + col] = make_float2(c[mt][nt][2], c[mt][nt][3]);
        }
    }
}

// ---------------------------------------------------------------------------
// Kernel B2: per-row stats + e materialization (causal-skipped).
// ---------------------------------------------------------------------------
__global__ __launch_bounds__(256) void stats_kernel()
{
    const int row  = blockIdx.x * 8 + (threadIdx.x >> 5);
    const int lane = threadIdx.x & 31;
    const int t    = row & (Tn - 1);
    const float* zr = &g_s[(size_t)row * Tn];

    float4 v[16];
    #pragma unroll
    for (int w = 0; w < 16; w++)
        v[w] = *(const float4*)&zr[w*128 + lane*4];

    float m = -1e30f;
    #pragma unroll
    for (int w = 0; w < 16; w++)
        m = fmaxf(m, fmaxf(fmaxf(v[w].x, v[w].y), fmaxf(v[w].z, v[w].w)));
    #pragma unroll
    for (int off = 16; off > 0; off >>= 1)
        m = fmaxf(m, __shfl_xor_sync(0xffffffffu, m, off));
    const float m8 = 8.f * m;

    float Z = 0.f;
    #pragma unroll
    for (int w = 0; w < 16; w++) {
        v[w].x = __expf(fmaf(v[w].x, 8.f, -m8));
        v[w].y = __expf(fmaf(v[w].y, 8.f, -m8));
        v[w].z = __expf(fmaf(v[w].z, 8.f, -m8));
        v[w].w = __expf(fmaf(v[w].w, 8.f, -m8));
        Z += v[w].x + v[w].y + v[w].z + v[w].w;
    }
    #pragma unroll
    for (int off = 16; off > 0; off >>= 1)
        Z += __shfl_xor_sync(0xffffffffu, Z, off);
    const float iz = 1.f / Z;

    const int wmax = t >> 7;    // last consumed 128-key group (warp-uniform)
    float den = 0.f;
    #pragma unroll
    for (int w = 0; w < 16; w++) {
        if (w <= wmax) {
            const int sbase = w*128 + lane*4;
            float e0 = (sbase + 0 <= t) ? __expf(v[w].x * iz) : 0.f;
            float e1 = (sbase + 1 <= t) ? __expf(v[w].y * iz) : 0.f;
            float e2 = (sbase + 2 <= t) ? __expf(v[w].z * iz) : 0.f;
            float e3 = (sbase + 3 <= t) ? __expf(v[w].w * iz) : 0.f;
            den += e0 + e1 + e2 + e3;
            u16 hi[4], lo[4];
            hi[0] = (u16)bfsplit(e0, lo[0]);
            hi[1] = (u16)bfsplit(e1, lo[1]);
            hi[2] = (u16)bfsplit(e2, lo[2]);
            hi[3] = (u16)bfsplit(e3, lo[3]);
            *(uint2*)&g_ehi[(size_t)row*Tn + sbase] = *(const uint2*)hi;
            *(uint2*)&g_elo[(size_t)row*Tn + sbase] = *(const uint2*)lo;
        }
    }
    #pragma unroll
    for (int off = 16; off > 0; off >>= 1)
        den += __shfl_xor_sync(0xffffffffu, den, off);

    if (lane == 0) g_iden[row] = 1.f / den;
}

// ---------------------------------------------------------------------------
// Kernel B3: split-s partial numerators — pure staged HMMA GEMM.
// ---------------------------------------------------------------------------
#define ESTR 40   // halves per e row (32 -> 40)
#define VSTR 72   // halves per v row (64 -> 72)

__global__ __launch_bounds__(256) void outp_mma()
{
    __shared__ u16 seh[128*ESTR], sel[128*ESTR];
    __shared__ u16 svh[32*VSTR],  svl[32*VSTR];

    const int chunk = blockIdx.x;
    const int row0  = blockIdx.y * 128;
    const int b     = row0 >> 11;
    const int t0    = row0 & (Tn - 1);
    const int sbeg  = chunk * CHUNK;
    if (sbeg > t0 + 127) return;
    const int send  = min(sbeg + CHUNK, t0 + 128);
    const int nk    = (send - sbeg) >> 5;

    const int tid  = threadIdx.x;
    const int wid  = tid >> 5;
    const int lane = tid & 31;
    const int wm   = wid & 3;
    const int wn   = wid >> 2;

    const uint32_t sb_eh = smem_u32(seh), sb_el = smem_u32(sel);
    const uint32_t sb_vh = smem_u32(svh), sb_vl = smem_u32(svl);

    float c[2][4][4];
    #pragma unroll
    for (int mt = 0; mt < 2; mt++)
        #pragma unroll
        for (int nt = 0; nt < 4; nt++)
            #pragma unroll
            for (int q = 0; q < 4; q++) c[mt][nt][q] = 0.f;

    const int lrow  = lane & 15;
    const int lcolb = (lane >> 4) * 16;

    for (int kt = 0; kt < nk; kt++) {
        const int s0 = sbeg + kt*32;
        __syncthreads();
        // e tiles: 128 rows x 32 s
        #pragma unroll
        for (int i = tid; i < 512; i += 256) {
            int r = i >> 2, c8 = (i & 3) * 8;
            size_t go = (size_t)(row0 + r)*Tn + s0 + c8;
            *(uint4*)&seh[r*ESTR + c8] = *(const uint4*)&g_ehi[go];
            *(uint4*)&sel[r*ESTR + c8] = *(const uint4*)&g_elo[go];
        }
        // V tiles: 32 s x 64 d
        {
            int r = tid >> 3, c8 = (tid & 7) * 8;
            size_t go = (size_t)(b*Tn + s0 + r)*HDn + c8;
            *(uint4*)&svh[r*VSTR + c8] = *(const uint4*)&g_vhi[go];
            *(uint4*)&svl[r*VSTR + c8] = *(const uint4*)&g_vlo[go];
        }
        __syncthreads();
        #pragma unroll
        for (int ks = 0; ks < 2; ks++) {
            uint32_t ah[2][4], al[2][4];
            #pragma unroll
            for (int mt = 0; mt < 2; mt++) {
                uint32_t base = (wm*32 + mt*16 + lrow)*(ESTR*2) + ks*32 + lcolb;
                ldsm4(ah[mt], sb_eh + base);
                ldsm4(al[mt], sb_el + base);
            }
            uint32_t bh[2][4], bl[2][4];
            #pragma unroll
            for (int ng = 0; ng < 2; ng++) {
                uint32_t base = (ks*16 + lrow)*(VSTR*2) + (wn*32 + ng*16)*2 + lcolb;
                ldsm4t(bh[ng], sb_vh + base);
                ldsm4t(bl[ng], sb_vl + base);
            }
            #pragma unroll
            for (int mt = 0; mt < 2; mt++) {
                #pragma unroll
                for (int ng = 0; ng < 2; ng++) {
                    float* c0 = c[mt][ng*2+0];
                    float* c1 = c[mt][ng*2+1];
                    mma16816(c0, ah[mt], bh[ng][0], bh[ng][1]);
                    mma16816(c1, ah[mt], bh[ng][2], bh[ng][3]);
                    mma16816(c0, ah[mt], bl[ng][0], bl[ng][1]);
                    mma16816(c1, ah[mt], bl[ng][2], bl[ng][3]);
                    mma16816(c0, al[mt], bh[ng][0], bh[ng][1]);
                    mma16816(c1, al[mt], bh[ng][2], bh[ng][3]);
                }
            }
        }
    }

    float* dst = &g_part[((size_t)chunk*NROWS + row0)*HDn];
    #pragma unroll
    for (int mt = 0; mt < 2; mt++) {
        #pragma unroll
        for (int nt = 0; nt < 4; nt++) {
            int r   = wm*32 + mt*16 + (lane >> 2);
            int col = wn*32 + nt*8 + (lane & 3)*2;
            *(float2*)&dst[(size_t)r*HDn + col]     = make_float2(c[mt][nt][0], c[mt][nt][1]);
            *(float2*)&dst[(size_t)(r+8)*HDn + col] = make_float2(c[mt][nt][2], c[mt][nt][3]);
        }
    }
}

// ---------------------------------------------------------------------------
// Kernel B4: finalize.
// ---------------------------------------------------------------------------
__global__ __launch_bounds__(256) void fin_kernel(float* __restrict__ out)
{
    const int idx = blockIdx.x * 256 + threadIdx.x;
    const int row = idx >> 4;
    const int d4  = (idx & 15) * 4;
    const int nch = (((row & (Tn-1)) | 127) / CHUNK) + 1;

    float4 s = make_float4(0.f, 0.f, 0.f, 0.f);
    for (int c = 0; c < nch; c++) {
        float4 p = *(const float4*)&g_part[((size_t)c*NROWS + row)*HDn + d4];
        s.x += p.x; s.y += p.y; s.z += p.z; s.w += p.w;
    }
    const float inv = g_iden[row];
    s.x *= inv; s.y *= inv; s.z *= inv; s.w *= inv;
    *(float4*)&out[(size_t)row*HDn + d4] = s;
}

// ---------------------------------------------------------------------------
extern "C" void kernel_launch(void* const* d_in, const int* in_sizes, int n_in,
                              void* d_out, int out_size)
{
    const float* x  = (const float*)d_in[0];
    const float* Wq = (const float*)d_in[1];
    const float* Wk = (const float*)d_in[2];
    const float* Wv = (const float*)d_in[3];
    float* out = (float*)d_out;

    cudaFuncSetAttribute(scores_mma, cudaFuncAttributeMaxDynamicSharedMemorySize, SC_SMEM);

    prep_x<<<(NROWS*Cn/8)/256, 256>>>(x);
    prep_w<<<(Cn*192/8 + 255)/256, 256>>>(Wq, Wk, Wv);
    qkv_mma<<<dim3(2, NROWS/64), 256>>>();
    scores_mma<<<dim3(Tn/128, NROWS/128), 256, SC_SMEM>>>();
    stats_kernel<<<NROWS/8, 256>>>();
    outp_mma<<<dim3(NCHUNK, NROWS/128), 256>>>();
    fin_kernel<<<(NROWS*HDn/4)/256, 256>>>(out);
}

// round 16
// speedup vs baseline: 1.2309x; 1.1560x over previous
#include <cuda_runtime.h>
#include <cuda_bf16.h>
#include <cstdint>

#define Bn 4
#define Tn 2048
#define Cn 1024
#define HDn 64
#define NROWS (Bn*Tn)       // 8192
#define CHUNK 256
#define NCHUNK (Tn/CHUNK)   // 8

typedef unsigned short u16;

// Scratch (__device__ globals — allowed)
__device__ __nv_bfloat16 g_whi[Cn*192];      // [k][Q|K|V cols]
__device__ __nv_bfloat16 g_wlo[Cn*192];
__device__ __nv_bfloat16 g_qhi[NROWS*HDn];
__device__ __nv_bfloat16 g_qlo[NROWS*HDn];
__device__ __nv_bfloat16 g_khi[NROWS*HDn];
__device__ __nv_bfloat16 g_klo[NROWS*HDn];
__device__ __nv_bfloat16 g_vhi[NROWS*HDn];
__device__ __nv_bfloat16 g_vlo[NROWS*HDn];
__device__ float g_s[NROWS*Tn];              // raw scores z (unscaled)
__device__ __nv_bfloat16 g_ehi[NROWS*Tn];    // e = exp(w1), causal, bf16 hi
__device__ __nv_bfloat16 g_elo[NROWS*Tn];    // bf16 lo
__device__ float g_iden[NROWS];              // 1 / causal denominator
__device__ float g_part[NCHUNK*NROWS*HDn];   // split-s partial numerators

// ---- mma.sync helpers ----------------------------------------------------
__device__ __forceinline__ uint32_t smem_u32(const void* p) {
    uint32_t a;
    asm("{ .reg .u64 t; cvta.to.shared.u64 t, %1; cvt.u32.u64 %0, t; }"
        : "=r"(a) : "l"(p));
    return a;
}
#define SW128(o) ((o) ^ (((o) >> 3) & 0x70))

__device__ __forceinline__ void ldsm4(uint32_t* r, uint32_t addr) {
    asm volatile("ldmatrix.sync.aligned.m8n8.x4.shared.b16 {%0,%1,%2,%3}, [%4];"
                 : "=r"(r[0]), "=r"(r[1]), "=r"(r[2]), "=r"(r[3]) : "r"(addr));
}
__device__ __forceinline__ void ldsm4t(uint32_t* r, uint32_t addr) {
    asm volatile("ldmatrix.sync.aligned.m8n8.x4.trans.shared.b16 {%0,%1,%2,%3}, [%4];"
                 : "=r"(r[0]), "=r"(r[1]), "=r"(r[2]), "=r"(r[3]) : "r"(addr));
}
__device__ __forceinline__ void mma16816(float* c, const uint32_t* a,
                                         uint32_t b0, uint32_t b1) {
    asm volatile("mma.sync.aligned.m16n8k16.row.col.f32.bf16.bf16.f32 "
                 "{%0,%1,%2,%3}, {%4,%5,%6,%7}, {%8,%9}, {%0,%1,%2,%3};"
                 : "+f"(c[0]), "+f"(c[1]), "+f"(c[2]), "+f"(c[3])
                 : "r"(a[0]), "r"(a[1]), "r"(a[2]), "r"(a[3]), "r"(b0), "r"(b1));
}
__device__ __forceinline__ uint32_t bfsplit(float v, u16& lo16) {
    __nv_bfloat16 hi = __float2bfloat16(v);
    __nv_bfloat16 lo = __float2bfloat16(v - __bfloat162float(hi));
    lo16 = *(const u16*)&lo;
    return *(const u16*)&hi;
}

// ---------------------------------------------------------------------------
// prep_w: split Wq|Wk|Wv into combined [k][192] bf16 hi/lo.
// ---------------------------------------------------------------------------
__global__ __launch_bounds__(256) void prep_w(
    const float* __restrict__ Wq, const float* __restrict__ Wk,
    const float* __restrict__ Wv)
{
    const int i8 = (blockIdx.x * 256 + threadIdx.x) * 8;   // over 1024*192
    if (i8 >= Cn*192) return;
    const int k    = i8 / 192;
    const int col8 = i8 - k*192;
    const float* W = (col8 < 64) ? Wq : ((col8 < 128) ? Wk : Wv);
    const float* src = &W[(size_t)k*HDn + (col8 & 63)];
    float4 a = *(const float4*)&src[0];
    float4 b = *(const float4*)&src[4];
    float v[8] = {a.x,a.y,a.z,a.w,b.x,b.y,b.z,b.w};
    u16 hi[8], lo[8];
    #pragma unroll
    for (int j = 0; j < 8; j++) { hi[j] = (u16)bfsplit(v[j], lo[j]); }
    *(uint4*)&g_whi[i8] = *(const uint4*)hi;
    *(uint4*)&g_wlo[i8] = *(const uint4*)lo;
}

// ---------------------------------------------------------------------------
// qkv_mma: [8192,1024]@[1024,192] HMMA 3-term split, double-buffered.
// grid (2 col-halves of 96, 128 row-blocks of 64); 256 thr; 8 warps 4m x 2n;
// warp tile 16 rows x 48 cols.  x read fp32 DIRECTLY; split to bf16 hi/lo in
// the store phase of the 2-stage pipeline (hidden behind HMMA).
// ---------------------------------------------------------------------------
#define XSTR 40    // halves per x row (32 -> 40)
#define WSTR 104   // halves per w row (96 -> 104)

__global__ __launch_bounds__(256) void qkv_mma(const float* __restrict__ x)
{
    __shared__ u16 sxh[2][64*XSTR], sxl[2][64*XSTR];
    __shared__ u16 swh[2][32*WSTR], swl[2][32*WSTR];

    const int ch   = blockIdx.x;
    const int row0 = blockIdx.y * 64;
    const int col0 = ch * 96;
    const int tid  = threadIdx.x;
    const int wid  = tid >> 5;
    const int lane = tid & 31;
    const int wm   = wid & 3;        // rows wm*16..+15
    const int wn   = wid >> 2;       // cols wn*48..+47

    float c[6][4];
    #pragma unroll
    for (int nt = 0; nt < 6; nt++)
        #pragma unroll
        for (int q = 0; q < 4; q++) c[nt][q] = 0.f;

    const int lrow  = lane & 15;
    const int lcolb = (lane >> 4) * 16;

    // staging indices (fixed per thread)
    const int xr = tid >> 2, xc8 = (tid & 3) * 8;          // 8 fp32 x elems
    const int wr0 = tid / 12,          wc0 = (tid % 12) * 8;      // w slot A
    const int wr1 = (tid + 256) / 12,  wc1 = ((tid + 256) % 12) * 8; // w slot B
    const bool hasw1 = (tid + 256) < 384;

    float4 px0, px1;
    uint4 pw_h0, pw_l0, pw_h1, pw_l1;

    // prefetch k0 = 0
    {
        const float* sx = &x[(size_t)(row0 + xr)*Cn + xc8];
        px0 = *(const float4*)&sx[0];
        px1 = *(const float4*)&sx[4];
        size_t gw0 = (size_t)wr0*192 + col0 + wc0;
        pw_h0 = *(const uint4*)&g_whi[gw0];
        pw_l0 = *(const uint4*)&g_wlo[gw0];
        if (hasw1) {
            size_t gw1 = (size_t)wr1*192 + col0 + wc1;
            pw_h1 = *(const uint4*)&g_whi[gw1];
            pw_l1 = *(const uint4*)&g_wlo[gw1];
        }
    }
    // split + store to buf 0
    {
        float vv[8] = {px0.x,px0.y,px0.z,px0.w,px1.x,px1.y,px1.z,px1.w};
        u16 hi[8], lo[8];
        #pragma unroll
        for (int j = 0; j < 8; j++) hi[j] = (u16)bfsplit(vv[j], lo[j]);
        *(uint4*)&sxh[0][xr*XSTR + xc8] = *(const uint4*)hi;
        *(uint4*)&sxl[0][xr*XSTR + xc8] = *(const uint4*)lo;
        *(uint4*)&swh[0][wr0*WSTR + wc0] = pw_h0;
        *(uint4*)&swl[0][wr0*WSTR + wc0] = pw_l0;
        if (hasw1) {
            *(uint4*)&swh[0][wr1*WSTR + wc1] = pw_h1;
            *(uint4*)&swl[0][wr1*WSTR + wc1] = pw_l1;
        }
    }
    __syncthreads();

    for (int it = 0; it < 32; it++) {
        const int cur = it & 1, nxt = cur ^ 1;
        // prefetch next tile (LDG before MMA, latency overlapped)
        if (it < 31) {
            const int k0 = (it + 1) * 32;
            const float* sx = &x[(size_t)(row0 + xr)*Cn + k0 + xc8];
            px0 = *(const float4*)&sx[0];
            px1 = *(const float4*)&sx[4];
            size_t gw0 = (size_t)(k0 + wr0)*192 + col0 + wc0;
            pw_h0 = *(const uint4*)&g_whi[gw0];
            pw_l0 = *(const uint4*)&g_wlo[gw0];
            if (hasw1) {
                size_t gw1 = (size_t)(k0 + wr1)*192 + col0 + wc1;
                pw_h1 = *(const uint4*)&g_whi[gw1];
                pw_l1 = *(const uint4*)&g_wlo[gw1];
            }
        }
        // MMA on current buffer
        const uint32_t sb_xh = smem_u32(sxh[cur]), sb_xl = smem_u32(sxl[cur]);
        const uint32_t sb_wh = smem_u32(swh[cur]), sb_wl = smem_u32(swl[cur]);
        #pragma unroll
        for (int ks = 0; ks < 2; ks++) {
            uint32_t ah[4], al[4];
            {
                uint32_t base = (wm*16 + lrow)*(XSTR*2) + ks*32 + lcolb;
                ldsm4(ah, sb_xh + base);
                ldsm4(al, sb_xl + base);
            }
            uint32_t bh[3][4], bl[3][4];
            #pragma unroll
            for (int ng = 0; ng < 3; ng++) {
                uint32_t base = (ks*16 + lrow)*(WSTR*2) + (wn*48 + ng*16)*2 + lcolb;
                ldsm4t(bh[ng], sb_wh + base);
                ldsm4t(bl[ng], sb_wl + base);
            }
            #pragma unroll
            for (int ng = 0; ng < 3; ng++) {
                float* c0 = c[ng*2+0];
                float* c1 = c[ng*2+1];
                mma16816(c0, ah, bh[ng][0], bh[ng][1]);
                mma16816(c1, ah, bh[ng][2], bh[ng][3]);
                mma16816(c0, ah, bl[ng][0], bl[ng][1]);
                mma16816(c1, ah, bl[ng][2], bl[ng][3]);
                mma16816(c0, al, bh[ng][0], bh[ng][1]);
                mma16816(c1, al, bh[ng][2], bh[ng][3]);
            }
        }
        // split + store prefetched tile into next buffer; one sync per iter
        if (it < 31) {
            float vv[8] = {px0.x,px0.y,px0.z,px0.w,px1.x,px1.y,px1.z,px1.w};
            u16 hi[8], lo[8];
            #pragma unroll
            for (int j = 0; j < 8; j++) hi[j] = (u16)bfsplit(vv[j], lo[j]);
            *(uint4*)&sxh[nxt][xr*XSTR + xc8] = *(const uint4*)hi;
            *(uint4*)&sxl[nxt][xr*XSTR + xc8] = *(const uint4*)lo;
            *(uint4*)&swh[nxt][wr0*WSTR + wc0] = pw_h0;
            *(uint4*)&swl[nxt][wr0*WSTR + wc0] = pw_l0;
            if (hasw1) {
                *(uint4*)&swh[nxt][wr1*WSTR + wc1] = pw_h1;
                *(uint4*)&swl[nxt][wr1*WSTR + wc1] = pw_l1;
            }
            __syncthreads();
        }
    }

    // epilogue: split to bf16 hi/lo, scatter to q/k/v
    #pragma unroll
    for (int nt = 0; nt < 6; nt++) {
        #pragma unroll
        for (int h = 0; h < 2; h++) {
            int r   = row0 + wm*16 + (lane >> 2) + h*8;
            int gc  = col0 + wn*48 + nt*8 + (lane & 3)*2;
            float v0 = c[nt][h*2+0], v1 = c[nt][h*2+1];
            u16 lo0, lo1;
            u16 hi0 = (u16)bfsplit(v0, lo0);
            u16 hi1 = (u16)bfsplit(v1, lo1);
            uint32_t hip = (uint32_t)hi0 | ((uint32_t)hi1 << 16);
            uint32_t lop = (uint32_t)lo0 | ((uint32_t)lo1 << 16);
            int dcol = gc & 63;
            size_t o = (size_t)r*HDn + dcol;
            if      (gc < 64)  { *(uint32_t*)&g_qhi[o] = hip; *(uint32_t*)&g_qlo[o] = lop; }
            else if (gc < 128) { *(uint32_t*)&g_khi[o] = hip; *(uint32_t*)&g_klo[o] = lop; }
            else               { *(uint32_t*)&g_vhi[o] = hip; *(uint32_t*)&g_vlo[o] = lop; }
        }
    }
}

// ---------------------------------------------------------------------------
// Kernel B1: scores via warp-level mma.sync (bf16 split, fp32 accum).
// ---------------------------------------------------------------------------
#define SC_QHI     0
#define SC_QLO     (SC_QHI + 16384)
#define SC_KHI     (SC_QLO + 16384)
#define SC_KLO     (SC_KHI + 16384)
#define SC_SMEM    (SC_KLO + 16384)

__device__ __forceinline__ void sc_load_tile(char* smem, int dstoff,
    const __nv_bfloat16* __restrict__ src, int row0, int tid)
{
    #pragma unroll
    for (int c = tid; c < 1024; c += 256) {
        int r = c >> 3, o = (c & 7) * 16;
        uint4 v = *(const uint4*)((const char*)(src + (size_t)(row0 + r)*HDn) + o);
        *(uint4*)(smem + dstoff + SW128(r*128 + o)) = v;
    }
}

__global__ __launch_bounds__(256) void scores_mma()
{
    extern __shared__ char smem[];
    const uint32_t sb = smem_u32(smem);
    const int tid  = threadIdx.x;
    const int wid  = tid >> 5;
    const int lane = tid & 31;

    const int s0    = blockIdx.x * 128;
    const int row0  = blockIdx.y * 128;
    const int b     = row0 >> 11;
    const int krow0 = b * Tn + s0;

    sc_load_tile(smem, SC_QHI, g_qhi, row0, tid);
    sc_load_tile(smem, SC_QLO, g_qlo, row0, tid);
    sc_load_tile(smem, SC_KHI, g_khi, krow0, tid);
    sc_load_tile(smem, SC_KLO, g_klo, krow0, tid);
    __syncthreads();

    const int wm = wid & 3;
    const int wn = wid >> 2;

    float c[2][8][4];
    #pragma unroll
    for (int mt = 0; mt < 2; mt++)
        #pragma unroll
        for (int nt = 0; nt < 8; nt++)
            #pragma unroll
            for (int q = 0; q < 4; q++) c[mt][nt][q] = 0.f;

    const int lrow = lane & 15;
    const int lcol = (lane >> 4) * 16;

    #pragma unroll
    for (int k = 0; k < 4; k++) {
        const int kb = k * 32;
        uint32_t ahi[2][4], alo[2][4];
        #pragma unroll
        for (int mt = 0; mt < 2; mt++) {
            int r = wm*32 + mt*16 + lrow;
            ldsm4(ahi[mt], sb + SC_QHI + SW128(r*128 + kb + lcol));
            ldsm4(alo[mt], sb + SC_QLO + SW128(r*128 + kb + lcol));
        }
        #pragma unroll
        for (int nt2 = 0; nt2 < 4; nt2++) {
            int r = wn*64 + nt2*16 + lrow;
            uint32_t bh[4], bl[4];
            ldsm4(bh, sb + SC_KHI + SW128(r*128 + kb + lcol));
            ldsm4(bl, sb + SC_KLO + SW128(r*128 + kb + lcol));
            #pragma unroll
            for (int mt = 0; mt < 2; mt++) {
                float* c0 = c[mt][nt2*2+0];
                float* c1 = c[mt][nt2*2+1];
                mma16816(c0, ahi[mt], bh[0], bh[2]);
                mma16816(c1, ahi[mt], bh[1], bh[3]);
                mma16816(c0, ahi[mt], bl[0], bl[2]);
                mma16816(c1, ahi[mt], bl[1], bl[3]);
                mma16816(c0, alo[mt], bh[0], bh[2]);
                mma16816(c1, alo[mt], bh[1], bh[3]);
            }
        }
    }

    #pragma unroll
    for (int mt = 0; mt < 2; mt++) {
        #pragma unroll
        for (int nt = 0; nt < 8; nt++) {
            int row = row0 + wm*32 + mt*16 + (lane >> 2);
            int col = s0 + wn*64 + nt*8 + (lane & 3)*2;
            *(float2*)&g_s[(size_t)row*Tn + col]     = make_float2(c[mt][nt][0], c[mt][nt][1]);
            *(float2*)&g_s[(size_t)(row+8)*Tn + col] = make_float2(c[mt][nt][2], c[mt][nt][3]);
        }
    }
}

// ---------------------------------------------------------------------------
// Kernel B2: per-row stats + e materialization (causal-skipped).
// ---------------------------------------------------------------------------
__global__ __launch_bounds__(256) void stats_kernel()
{
    const int row  = blockIdx.x * 8 + (threadIdx.x >> 5);
    const int lane = threadIdx.x & 31;
    const int t    = row & (Tn - 1);
    const float* zr = &g_s[(size_t)row * Tn];

    float4 v[16];
    #pragma unroll
    for (int w = 0; w < 16; w++)
        v[w] = *(const float4*)&zr[w*128 + lane*4];

    float m = -1e30f;
    #pragma unroll
    for (int w = 0; w < 16; w++)
        m = fmaxf(m, fmaxf(fmaxf(v[w].x, v[w].y), fmaxf(v[w].z, v[w].w)));
    #pragma unroll
    for (int off = 16; off > 0; off >>= 1)
        m = fmaxf(m, __shfl_xor_sync(0xffffffffu, m, off));
    const float m8 = 8.f * m;

    float Z = 0.f;
    #pragma unroll
    for (int w = 0; w < 16; w++) {
        v[w].x = __expf(fmaf(v[w].x, 8.f, -m8));
        v[w].y = __expf(fmaf(v[w].y, 8.f, -m8));
        v[w].z = __expf(fmaf(v[w].z, 8.f, -m8));
        v[w].w = __expf(fmaf(v[w].w, 8.f, -m8));
        Z += v[w].x + v[w].y + v[w].z + v[w].w;
    }
    #pragma unroll
    for (int off = 16; off > 0; off >>= 1)
        Z += __shfl_xor_sync(0xffffffffu, Z, off);
    const float iz = 1.f / Z;

    const int wmax = t >> 7;    // last consumed 128-key group (warp-uniform)
    float den = 0.f;
    #pragma unroll
    for (int w = 0; w < 16; w++) {
        if (w <= wmax) {
            const int sbase = w*128 + lane*4;
            float e0 = (sbase + 0 <= t) ? __expf(v[w].x * iz) : 0.f;
            float e1 = (sbase + 1 <= t) ? __expf(v[w].y * iz) : 0.f;
            float e2 = (sbase + 2 <= t) ? __expf(v[w].z * iz) : 0.f;
            float e3 = (sbase + 3 <= t) ? __expf(v[w].w * iz) : 0.f;
            den += e0 + e1 + e2 + e3;
            u16 hi[4], lo[4];
            hi[0] = (u16)bfsplit(e0, lo[0]);
            hi[1] = (u16)bfsplit(e1, lo[1]);
            hi[2] = (u16)bfsplit(e2, lo[2]);
            hi[3] = (u16)bfsplit(e3, lo[3]);
            *(uint2*)&g_ehi[(size_t)row*Tn + sbase] = *(const uint2*)hi;
            *(uint2*)&g_elo[(size_t)row*Tn + sbase] = *(const uint2*)lo;
        }
    }
    #pragma unroll
    for (int off = 16; off > 0; off >>= 1)
        den += __shfl_xor_sync(0xffffffffu, den, off);

    if (lane == 0) g_iden[row] = 1.f / den;
}

// ---------------------------------------------------------------------------
// Kernel B3: split-s partial numerators — pure staged HMMA GEMM.
// ---------------------------------------------------------------------------
#define ESTR 40   // halves per e row (32 -> 40)
#define VSTR 72   // halves per v row (64 -> 72)

__global__ __launch_bounds__(256) void outp_mma()
{
    __shared__ u16 seh[128*ESTR], sel[128*ESTR];
    __shared__ u16 svh[32*VSTR],  svl[32*VSTR];

    const int chunk = blockIdx.x;
    const int row0  = blockIdx.y * 128;
    const int b     = row0 >> 11;
    const int t0    = row0 & (Tn - 1);
    const int sbeg  = chunk * CHUNK;
    if (sbeg > t0 + 127) return;
    const int send  = min(sbeg + CHUNK, t0 + 128);
    const int nk    = (send - sbeg) >> 5;

    const int tid  = threadIdx.x;
    const int wid  = tid >> 5;
    const int lane = tid & 31;
    const int wm   = wid & 3;
    const int wn   = wid >> 2;

    const uint32_t sb_eh = smem_u32(seh), sb_el = smem_u32(sel);
    const uint32_t sb_vh = smem_u32(svh), sb_vl = smem_u32(svl);

    float c[2][4][4];
    #pragma unroll
    for (int mt = 0; mt < 2; mt++)
        #pragma unroll
        for (int nt = 0; nt < 4; nt++)
            #pragma unroll
            for (int q = 0; q < 4; q++) c[mt][nt][q] = 0.f;

    const int lrow  = lane & 15;
    const int lcolb = (lane >> 4) * 16;

    for (int kt = 0; kt < nk; kt++) {
        const int s0 = sbeg + kt*32;
        __syncthreads();
        // e tiles: 128 rows x 32 s
        #pragma unroll
        for (int i = tid; i < 512; i += 256) {
            int r = i >> 2, c8 = (i & 3) * 8;
            size_t go = (size_t)(row0 + r)*Tn + s0 + c8;
            *(uint4*)&seh[r*ESTR + c8] = *(const uint4*)&g_ehi[go];
            *(uint4*)&sel[r*ESTR + c8] = *(const uint4*)&g_elo[go];
        }
        // V tiles: 32 s x 64 d
        {
            int r = tid >> 3, c8 = (tid & 7) * 8;
            size_t go = (size_t)(b*Tn + s0 + r)*HDn + c8;
            *(uint4*)&svh[r*VSTR + c8] = *(const uint4*)&g_vhi[go];
            *(uint4*)&svl[r*VSTR + c8] = *(const uint4*)&g_vlo[go];
        }
        __syncthreads();
        #pragma unroll
        for (int ks = 0; ks < 2; ks++) {
            uint32_t ah[2][4], al[2][4];
            #pragma unroll
            for (int mt = 0; mt < 2; mt++) {
                uint32_t base = (wm*32 + mt*16 + lrow)*(ESTR*2) + ks*32 + lcolb;
                ldsm4(ah[mt], sb_eh + base);
                ldsm4(al[mt], sb_el + base);
            }
            uint32_t bh[2][4], bl[2][4];
            #pragma unroll
            for (int ng = 0; ng < 2; ng++) {
                uint32_t base = (ks*16 + lrow)*(VSTR*2) + (wn*32 + ng*16)*2 + lcolb;
                ldsm4t(bh[ng], sb_vh + base);
                ldsm4t(bl[ng], sb_vl + base);
            }
            #pragma unroll
            for (int mt = 0; mt < 2; mt++) {
                #pragma unroll
                for (int ng = 0; ng < 2; ng++) {
                    float* c0 = c[mt][ng*2+0];
                    float* c1 = c[mt][ng*2+1];
                    mma16816(c0, ah[mt], bh[ng][0], bh[ng][1]);
                    mma16816(c1, ah[mt], bh[ng][2], bh[ng][3]);
                    mma16816(c0, ah[mt], bl[ng][0], bl[ng][1]);
                    mma16816(c1, ah[mt], bl[ng][2], bl[ng][3]);
                    mma16816(c0, al[mt], bh[ng][0], bh[ng][1]);
                    mma16816(c1, al[mt], bh[ng][2], bh[ng][3]);
                }
            }
        }
    }

    float* dst = &g_part[((size_t)chunk*NROWS + row0)*HDn];
    #pragma unroll
    for (int mt = 0; mt < 2; mt++) {
        #pragma unroll
        for (int nt = 0; nt < 4; nt++) {
            int r   = wm*32 + mt*16 + (lane >> 2);
            int col = wn*32 + nt*8 + (lane & 3)*2;
            *(float2*)&dst[(size_t)r*HDn + col]     = make_float2(c[mt][nt][0], c[mt][nt][1]);
            *(float2*)&dst[(size_t)(r+8)*HDn + col] = make_float2(c[mt][nt][2], c[mt][nt][3]);
        }
    }
}

// ---------------------------------------------------------------------------
// Kernel B4: finalize.
// ---------------------------------------------------------------------------
__global__ __launch_bounds__(256) void fin_kernel(float* __restrict__ out)
{
    const int idx = blockIdx.x * 256 + threadIdx.x;
    const int row = idx >> 4;
    const int d4  = (idx & 15) * 4;
    const int nch = (((row & (Tn-1)) | 127) / CHUNK) + 1;

    float4 s = make_float4(0.f, 0.f, 0.f, 0.f);
    for (int c = 0; c < nch; c++) {
        float4 p = *(const float4*)&g_part[((size_t)c*NROWS + row)*HDn + d4];
        s.x += p.x; s.y += p.y; s.z += p.z; s.w += p.w;
    }
    const float inv = g_iden[row];
    s.x *= inv; s.y *= inv; s.z *= inv; s.w *= inv;
    *(float4*)&out[(size_t)row*HDn + d4] = s;
}

// ---------------------------------------------------------------------------
extern "C" void kernel_launch(void* const* d_in, const int* in_sizes, int n_in,
                              void* d_out, int out_size)
{
    const float* x  = (const float*)d_in[0];
    const float* Wq = (const float*)d_in[1];
    const float* Wk = (const float*)d_in[2];
    const float* Wv = (const float*)d_in[3];
    float* out = (float*)d_out;

    cudaFuncSetAttribute(scores_mma, cudaFuncAttributeMaxDynamicSharedMemorySize, SC_SMEM);

    prep_w<<<(Cn*192/8 + 255)/256, 256>>>(Wq, Wk, Wv);
    qkv_mma<<<dim3(2, NROWS/64), 256>>>(x);
    scores_mma<<<dim3(Tn/128, NROWS/128), 256, SC_SMEM>>>();
    stats_kernel<<<NROWS/8, 256>>>();
    outp_mma<<<dim3(NCHUNK, NROWS/128), 256>>>();
    fin_kernel<<<(NROWS*HDn/4)/256, 256>>>(out);
}